// round 6
// baseline (speedup 1.0000x reference)
#include <cuda_runtime.h>
#include <math.h>
#include <stdint.h>

#define M_ROWS 16384
#define K1 1024
#define N1 512
#define NANC 9
#define NBOX (M_ROWS*NANC)          /* 147456 */
#define PRE_NMS 6000
#define POST_NMS 300
#define IOU_THR 0.7f
#define REG_OFF (M_ROWS*NANC)            /* 147456 */
#define PROP_OFF (REG_OFF + M_ROWS*NANC*4) /* 737280 */
#define SEL_BLOCKS 288
#define NWORDS 188                      /* ceil(6000/32) */
#define SORT_N 8192

// ---------------- scratch (device globals; no allocation) ----------------
__device__ float g_h[M_ROWS*N1];            // bottleneck activations (32MB)
__device__ float g_boxes[NBOX*4];           // decoded+clipped boxes
__device__ unsigned long long g_keys[NBOX]; // (score_bits<<32)|~idx
__device__ unsigned long long g_ckeys[PRE_NMS];
__device__ float g_sboxes[PRE_NMS*4];       // boxes in sorted (score-desc) order
__device__ unsigned int g_mask[PRE_NMS*NWORDS]; // pairwise iou>thr bitmask (4.5MB)
__device__ unsigned int g_hist[256];
__device__ unsigned long long g_prefix;
__device__ int g_krem;
__device__ int g_count;
__device__ unsigned int g_bar_count;
__device__ unsigned int g_epoch;

// ================= helpers =================
__device__ __forceinline__ uint32_t smem_u32(const void* p) {
    uint32_t a;
    asm("{ .reg .u64 t; cvta.to.shared.u64 t, %1; cvt.u32.u64 %0, t; }" : "=r"(a) : "l"(p));
    return a;
}
__device__ __forceinline__ void split_tf32(float x, uint32_t& hi, uint32_t& lo) {
    hi = __float_as_uint(x) & 0xFFFFE000u;
    lo = __float_as_uint(x - __uint_as_float(hi));
}
__device__ __forceinline__ void mma_tf32(float* c, const uint32_t* a, uint32_t b0, uint32_t b1) {
    asm volatile(
        "mma.sync.aligned.m16n8k8.row.col.f32.tf32.tf32.f32 "
        "{%0,%1,%2,%3}, {%4,%5,%6,%7}, {%8,%9}, {%0,%1,%2,%3};"
        : "+f"(c[0]), "+f"(c[1]), "+f"(c[2]), "+f"(c[3])
        : "r"(a[0]), "r"(a[1]), "r"(a[2]), "r"(a[3]), "r"(b0), "r"(b1));
}
__device__ __forceinline__ void cp_async16(uint32_t dst, const void* src) {
    asm volatile("cp.async.ca.shared.global [%0], [%1], 16;" :: "r"(dst), "l"(src) : "memory");
}
__device__ __forceinline__ unsigned ld_cg_u32(const unsigned* p) {
    unsigned v;
    asm volatile("ld.global.cg.u32 %0, [%1];" : "=r"(v) : "l"(p) : "memory");
    return v;
}

// ================= kernel 1: split-TF32 warp-MMA bottleneck GEMM =================
#define PADA 36
#define PADB 136
#define A_BUF_BYTES (128*PADA*4)
#define B_BUF_BYTES (32*PADB*4)
#define GEMM_SMEM (2*A_BUF_BYTES + 2*B_BUF_BYTES)

__global__ __launch_bounds__(256, 2)
void gemm_bneck_mma(const float* __restrict__ A, const float* __restrict__ W,
                    const float* __restrict__ bias) {
    extern __shared__ float sm[];
    float* As = sm;
    float* Bs = sm + 2*128*PADA;
    const uint32_t sA = smem_u32(As);
    const uint32_t sB = smem_u32(Bs);

    const int tid = threadIdx.x;
    const int lane = tid & 31;
    const int wid = tid >> 5;
    const int m0 = blockIdx.y * 128;
    const int n0 = blockIdx.x * 128;
    const int mrow = (wid & 3) * 32;
    const int ncol = (wid >> 2) * 64;
    const int quad = lane >> 2;
    const int tq = lane & 3;

    float c[2][8][4];
#pragma unroll
    for (int mt = 0; mt < 2; mt++)
#pragma unroll
        for (int nt = 0; nt < 8; nt++)
#pragma unroll
            for (int j = 0; j < 4; j++) c[mt][nt][j] = 0.f;

    auto prefetch = [&](int s, int buf) {
        const int k0 = s * 32;
#pragma unroll
        for (int i = 0; i < 4; i++) {
            int idx = tid + i * 256;
            int r = idx >> 3, c4 = idx & 7;
            cp_async16(sA + (uint32_t)buf * A_BUF_BYTES + (uint32_t)(r * PADA + c4 * 4) * 4,
                       A + (size_t)(m0 + r) * K1 + k0 + c4 * 4);
        }
#pragma unroll
        for (int i = 0; i < 4; i++) {
            int idx = tid + i * 256;
            int r = idx >> 5, c4 = idx & 31;
            cp_async16(sB + (uint32_t)buf * B_BUF_BYTES + (uint32_t)(r * PADB + c4 * 4) * 4,
                       W + (size_t)(k0 + r) * N1 + n0 + c4 * 4);
        }
        asm volatile("cp.async.commit_group;" ::: "memory");
    };

    prefetch(0, 0);

    for (int s = 0; s < 32; s++) {
        const int buf = s & 1;
        if (s < 31) {
            prefetch(s + 1, buf ^ 1);
            asm volatile("cp.async.wait_group 1;" ::: "memory");
        } else {
            asm volatile("cp.async.wait_group 0;" ::: "memory");
        }
        __syncthreads();

        const float* Ab = As + buf * (128 * PADA);
        const float* Bb = Bs + buf * (32 * PADB);

#pragma unroll
        for (int kk = 0; kk < 4; kk++) {
            uint32_t ah[2][4], al[2][4];
#pragma unroll
            for (int mt = 0; mt < 2; mt++) {
                const int rbase = mrow + mt * 16 + quad;
                const int cbase = kk * 8 + tq;
                float r0 = Ab[(rbase)     * PADA + cbase];
                float r1 = Ab[(rbase + 8) * PADA + cbase];
                float r2 = Ab[(rbase)     * PADA + cbase + 4];
                float r3 = Ab[(rbase + 8) * PADA + cbase + 4];
                split_tf32(r0, ah[mt][0], al[mt][0]);
                split_tf32(r1, ah[mt][1], al[mt][1]);
                split_tf32(r2, ah[mt][2], al[mt][2]);
                split_tf32(r3, ah[mt][3], al[mt][3]);
            }
#pragma unroll
            for (int nt = 0; nt < 8; nt++) {
                const int n = ncol + nt * 8 + quad;
                float b0r = Bb[(kk * 8 + tq)     * PADB + n];
                float b1r = Bb[(kk * 8 + tq + 4) * PADB + n];
                uint32_t bh0, bl0, bh1, bl1;
                split_tf32(b0r, bh0, bl0);
                split_tf32(b1r, bh1, bl1);
#pragma unroll
                for (int mt = 0; mt < 2; mt++) {
                    mma_tf32(c[mt][nt], ah[mt], bh0, bh1);
                    mma_tf32(c[mt][nt], ah[mt], bl0, bl1);
                    mma_tf32(c[mt][nt], al[mt], bh0, bh1);
                }
            }
        }
        __syncthreads();
    }

#pragma unroll
    for (int nt = 0; nt < 8; nt++) {
        const int nc = n0 + ncol + nt * 8 + 2 * tq;
        const float bia0 = __ldg(&bias[nc]);
        const float bia1 = __ldg(&bias[nc + 1]);
#pragma unroll
        for (int mt = 0; mt < 2; mt++) {
            const int row0 = m0 + mrow + mt * 16 + quad;
            float2 v01, v23;
            v01.x = fmaxf(c[mt][nt][0] + bia0, 0.f);
            v01.y = fmaxf(c[mt][nt][1] + bia1, 0.f);
            v23.x = fmaxf(c[mt][nt][2] + bia0, 0.f);
            v23.y = fmaxf(c[mt][nt][3] + bia1, 0.f);
            *(float2*)&g_h[(size_t)row0 * N1 + nc]       = v01;
            *(float2*)&g_h[(size_t)(row0 + 8) * N1 + nc] = v23;
        }
    }
}

// ---------------- kernel 2: head GEMM + sigmoid + box decode ----------------
__global__ __launch_bounds__(256, 4)
void head_kernel(const float* __restrict__ ancs,
                 const float* __restrict__ wc, const float* __restrict__ bc,
                 const float* __restrict__ wr, const float* __restrict__ br,
                 float* __restrict__ out) {
    __shared__ float Hs[32][64];
    __shared__ float Ws[32][48];
    __shared__ float Os[64][48];
    const int tid = threadIdx.x;
    const int tx = tid & 15;
    const int ty = tid >> 4;
    const int gr0 = blockIdx.x * 64;

    if (blockIdx.x == 0 && tid == 0) {
        g_prefix = 0ull;
        g_krem = PRE_NMS;
        g_count = 0;
        g_bar_count = 0u;
        g_epoch = 0u;
    }

    float acc[4][3];
#pragma unroll
    for (int i = 0; i < 4; i++)
#pragma unroll
        for (int j = 0; j < 3; j++) acc[i][j] = 0.f;

    for (int k0 = 0; k0 < N1; k0 += 32) {
#pragma unroll
        for (int v = 0; v < 2; v++) {
            int lin = tid * 8 + v * 4;
            int r = lin >> 5;
            int c = lin & 31;
            float4 h4 = *(const float4*)&g_h[(size_t)(gr0 + r) * N1 + k0 + c];
            Hs[c + 0][r] = h4.x; Hs[c + 1][r] = h4.y;
            Hs[c + 2][r] = h4.z; Hs[c + 3][r] = h4.w;
        }
        for (int idx = tid; idx < 32 * 48; idx += 256) {
            int r = idx / 48, o = idx % 48;
            float v = 0.f;
            if (o < 9)       v = wc[(size_t)(k0 + r) * 9 + o];
            else if (o < 45) v = wr[(size_t)(k0 + r) * 36 + (o - 9)];
            Ws[r][o] = v;
        }
        __syncthreads();
#pragma unroll
        for (int k = 0; k < 32; k++) {
            float a0 = Hs[k][ty * 4 + 0], a1 = Hs[k][ty * 4 + 1];
            float a2 = Hs[k][ty * 4 + 2], a3 = Hs[k][ty * 4 + 3];
            float b0 = Ws[k][tx * 3 + 0], b1 = Ws[k][tx * 3 + 1], b2 = Ws[k][tx * 3 + 2];
            acc[0][0] += a0 * b0; acc[0][1] += a0 * b1; acc[0][2] += a0 * b2;
            acc[1][0] += a1 * b0; acc[1][1] += a1 * b1; acc[1][2] += a1 * b2;
            acc[2][0] += a2 * b0; acc[2][1] += a2 * b1; acc[2][2] += a2 * b2;
            acc[3][0] += a3 * b0; acc[3][1] += a3 * b1; acc[3][2] += a3 * b2;
        }
        __syncthreads();
    }
#pragma unroll
    for (int i = 0; i < 4; i++)
#pragma unroll
        for (int j = 0; j < 3; j++) {
            int o = tx * 3 + j;
            float bia = (o < 9) ? bc[o] : ((o < 45) ? br[o - 9] : 0.f);
            Os[ty * 4 + i][o] = acc[i][j] + bia;
        }
    __syncthreads();
    for (int idx = tid; idx < 64 * 45; idx += 256) {
        int r = idx / 45, o = idx % 45;
        float v = Os[r][o];
        int grow = gr0 + r;
        if (o < 9) out[(size_t)grow * 9 + o] = 1.f / (1.f + expf(-v));
        else       out[REG_OFF + (size_t)grow * 36 + (o - 9)] = v;
    }
    for (int t = tid; t < 64 * 9; t += 256) {
        int r = t / 9, a = t % 9;
        int gi = (gr0 + r) * 9 + a;
        float logit = Os[r][a];
        float score = 1.f / (1.f + expf(-logit));
        float tx_ = Os[r][9 + a * 4 + 0];
        float ty_ = Os[r][9 + a * 4 + 1];
        float tw_ = Os[r][9 + a * 4 + 2];
        float th_ = Os[r][9 + a * 4 + 3];
        float acx = ancs[(size_t)gi * 4 + 0];
        float acy = ancs[(size_t)gi * 4 + 1];
        float aw  = ancs[(size_t)gi * 4 + 2];
        float ah  = ancs[(size_t)gi * 4 + 3];
        float cx = acx + tx_ * aw;
        float cy = acy + ty_ * ah;
        float ww = aw * expf(tw_);
        float hh = ah * expf(th_);
        float x1 = fminf(fmaxf(cx - ww * 0.5f, 0.f), 1.f);
        float y1 = fminf(fmaxf(cy - hh * 0.5f, 0.f), 1.f);
        float x2 = fminf(fmaxf(cx + ww * 0.5f, 0.f), 1.f);
        float y2 = fminf(fmaxf(cy + hh * 0.5f, 0.f), 1.f);
        g_boxes[(size_t)gi * 4 + 0] = x1;
        g_boxes[(size_t)gi * 4 + 1] = y1;
        g_boxes[(size_t)gi * 4 + 2] = x2;
        g_boxes[(size_t)gi * 4 + 3] = y2;
        unsigned sb = __float_as_uint(score);
        g_keys[gi] = ((unsigned long long)sb << 32) | (unsigned long long)(~(unsigned)gi);
    }
}

// ===== selection: exact 64-bit radix select + compact, ONE kernel =====
__global__ __launch_bounds__(256)
void select_all() {
    __shared__ unsigned int sh[256];
    __shared__ unsigned long long s_pref;
    __shared__ int s_last;
    const int tid = threadIdx.x;
    const int gs = gridDim.x * blockDim.x;
    const int gi = blockIdx.x * blockDim.x + tid;
    unsigned myep = 0;

    for (int p = 7; p >= 0; p--) {
        const int shift = p * 8;
        if (tid == 0)
            s_pref = (p == 7) ? 0ull : atomicAdd(&g_prefix, 0ull);
        sh[tid] = 0u;
        __syncthreads();
        const unsigned long long pref = s_pref;
        const unsigned long long mask = (p == 7) ? 0ull : (~0ull << (shift + 8));

        for (int i = gi; i < NBOX; i += gs) {
            unsigned long long k = g_keys[i];
            if (((k ^ pref) & mask) == 0ull)
                atomicAdd(&sh[(unsigned)(k >> shift) & 255u], 1u);
        }
        __syncthreads();
        if (sh[tid]) atomicAdd(&g_hist[tid], sh[tid]);
        __threadfence();
        myep++;

        if (tid == 0)
            s_last = (atomicAdd(&g_bar_count, 1u) == (unsigned)(gridDim.x - 1)) ? 1 : 0;
        __syncthreads();

        if (s_last) {
            sh[tid] = atomicAdd(&g_hist[tid], 0u);
            __syncthreads();
            if (tid == 0) {
                int k = atomicAdd(&g_krem, 0);
                int b = 255;
                for (; b >= 0; --b) {
                    int c = (int)sh[b];
                    if (c >= k) break;
                    k -= c;
                }
                if (b < 0) b = 0;
                atomicOr(&g_prefix, ((unsigned long long)(unsigned)b) << shift);
                atomicExch(&g_krem, k);
            }
            atomicExch(&g_hist[tid], 0u);
            __threadfence();
            __syncthreads();
            if (tid == 0) {
                atomicExch(&g_bar_count, 0u);
                __threadfence();
                atomicAdd(&g_epoch, 1u);
            }
        }
        if (tid == 0) {
            while (ld_cg_u32(&g_epoch) < myep) __nanosleep(64);
        }
        __syncthreads();
    }

    if (tid == 0) s_pref = atomicAdd(&g_prefix, 0ull);
    __syncthreads();
    const unsigned long long thr = s_pref;
    for (int i = gi; i < NBOX; i += gs) {
        unsigned long long k = g_keys[i];
        if (k >= thr) {
            int pos = atomicAdd(&g_count, 1);
            if (pos < PRE_NMS) g_ckeys[pos] = k;
        }
    }
}

// ===== NMS stage 1: bitonic sort 6000 keys desc (pad to 8192), gather boxes =====
__global__ __launch_bounds__(1024, 1)
void sort_kernel() {
    extern __shared__ unsigned long long sk[];   // 8192 * 8 = 64KB
    const int tid = threadIdx.x;
    const int nvalid = min(g_count, PRE_NMS);

#pragma unroll
    for (int j = 0; j < SORT_N / 1024; j++) {
        int idx = tid + j * 1024;
        sk[idx] = (idx < nvalid) ? g_ckeys[idx] : 0ull;
    }
    __syncthreads();

    // ascending bitonic sort; read back reversed for descending
    for (int k = 2; k <= SORT_N; k <<= 1) {
        for (int j = k >> 1; j > 0; j >>= 1) {
#pragma unroll
            for (int t = 0; t < SORT_N / 1024; t++) {
                int i = tid + t * 1024;
                int ixj = i ^ j;
                if (ixj > i) {
                    unsigned long long a = sk[i], b = sk[ixj];
                    bool up = ((i & k) == 0);
                    if (up ? (a > b) : (a < b)) { sk[i] = b; sk[ixj] = a; }
                }
            }
            __syncthreads();
        }
    }

    // gather boxes in sorted order: rank r -> sk[SORT_N-1-r]
    for (int r = tid; r < PRE_NMS; r += 1024) {
        unsigned long long key = sk[SORT_N - 1 - r];
        float4 b = make_float4(0.f, 0.f, 0.f, 0.f);
        if (key != 0ull) {
            unsigned gi = ~(unsigned)key;
            b = *(const float4*)&g_boxes[(size_t)gi * 4];
        }
        *(float4*)&g_sboxes[(size_t)r * 4] = b;
    }
}

// ===== NMS stage 2: pairwise IoU bitmask, fully parallel =====
#define MASK_ROWS 64
__global__ __launch_bounds__(256, 1)
void mask_kernel() {
    extern __shared__ float4 sbox[];   // 6000 * 16 = 96000 B
    const int tid = threadIdx.x;
    for (int i = tid; i < PRE_NMS; i += 256)
        sbox[i] = *(const float4*)&g_sboxes[(size_t)i * 4];
    __syncthreads();

    const int i0 = blockIdx.x * MASK_ROWS;
    for (int p = tid; p < MASK_ROWS * NWORDS; p += 256) {
        const int li = p / NWORDS;
        const int w = p % NWORDS;
        const int i = i0 + li;
        if (i >= PRE_NMS) break;
        const float4 bi = sbox[i];
        const float ai = (bi.z - bi.x) * (bi.w - bi.y);
        unsigned m = 0u;
        const int jbase = w * 32;
        const int jmax = min(32, PRE_NMS - jbase);
#pragma unroll 4
        for (int jj = 0; jj < jmax; jj++) {
            const float4 bj = sbox[jbase + jj];
            float iw = fminf(bi.z, bj.z) - fmaxf(bi.x, bj.x);
            float ih = fminf(bi.w, bj.w) - fmaxf(bi.y, bj.y);
            iw = fmaxf(iw, 0.f);
            ih = fmaxf(ih, 0.f);
            const float inter = iw * ih;
            const float aj = (bj.z - bj.x) * (bj.w - bj.y);
            const float uni = ai + aj - inter;
            const float iou = (uni > 0.f) ? inter / uni : 0.f;
            if (iou > IOU_THR) m |= (1u << jj);
        }
        g_mask[(size_t)i * NWORDS + w] = m;
    }
}

// ===== NMS stage 3: greedy scan over bitmask (only serial part) =====
__global__ __launch_bounds__(256, 1)
void scan_kernel(float* __restrict__ out) {
    __shared__ unsigned removed[NWORDS];
    __shared__ int s_win;
    const int tid = threadIdx.x;
    const int nvalid = min(g_count, PRE_NMS);

    if (tid < NWORDS) {
        // mark padding slots (>= nvalid) as removed
        unsigned init = 0u;
        int base = tid * 32;
        if (base + 32 > nvalid) {
            for (int b = 0; b < 32; b++)
                if (base + b >= nvalid) init |= (1u << b);
        }
        removed[tid] = init;
    }
    __syncthreads();

    int cw = 0;   // cursor word (only meaningful in thread 0; monotonic)
    int done_at = POST_NMS;
    for (int it = 0; it < POST_NMS; it++) {
        if (tid == 0) {
            int win = -1;
            for (; cw < NWORDS; cw++) {
                unsigned u = ~removed[cw];
                if (u) { win = cw * 32 + (__ffs(u) - 1); break; }
            }
            s_win = win;
        }
        __syncthreads();
        const int i = s_win;
        if (i < 0) { done_at = it; break; }
        if (tid == 0) {
            float4 b = *(const float4*)&g_sboxes[(size_t)i * 4];
            out[PROP_OFF + it * 4 + 0] = b.x;
            out[PROP_OFF + it * 4 + 1] = b.y;
            out[PROP_OFF + it * 4 + 2] = b.z;
            out[PROP_OFF + it * 4 + 3] = b.w;
        }
        if (tid < NWORDS)
            removed[tid] |= g_mask[(size_t)i * NWORDS + tid];   // self-bit is set (iou=1)
        __syncthreads();
    }
    for (int idx = done_at * 4 + tid; idx < POST_NMS * 4; idx += 256)
        out[PROP_OFF + idx] = 0.f;
}

// ---------------- launcher ----------------
extern "C" void kernel_launch(void* const* d_in, const int* in_sizes, int n_in,
                              void* d_out, int out_size) {
    const float* feats   = (const float*)d_in[0];
    const float* ancs    = (const float*)d_in[1];
    const float* w_bneck = (const float*)d_in[3];
    const float* b_bneck = (const float*)d_in[4];
    const float* w_cls   = (const float*)d_in[5];
    const float* b_cls   = (const float*)d_in[6];
    const float* w_reg   = (const float*)d_in[7];
    const float* b_reg   = (const float*)d_in[8];
    float* out = (float*)d_out;

    cudaFuncSetAttribute(gemm_bneck_mma, cudaFuncAttributeMaxDynamicSharedMemorySize, GEMM_SMEM);
    cudaFuncSetAttribute(sort_kernel, cudaFuncAttributeMaxDynamicSharedMemorySize, SORT_N * 8);
    cudaFuncSetAttribute(mask_kernel, cudaFuncAttributeMaxDynamicSharedMemorySize, PRE_NMS * 16);

    gemm_bneck_mma<<<dim3(4, 128), 256, GEMM_SMEM>>>(feats, w_bneck, b_bneck);
    head_kernel<<<M_ROWS / 64, 256>>>(ancs, w_cls, b_cls, w_reg, b_reg, out);
    select_all<<<SEL_BLOCKS, 256>>>();
    sort_kernel<<<1, 1024, SORT_N * 8>>>();
    mask_kernel<<<(PRE_NMS + MASK_ROWS - 1) / MASK_ROWS, 256, PRE_NMS * 16>>>();
    scan_kernel<<<1, 256>>>(out);
}

// round 7
// speedup vs baseline: 1.2666x; 1.2666x over previous
#include <cuda_runtime.h>
#include <math.h>
#include <stdint.h>

#define M_ROWS 16384
#define K1 1024
#define N1 512
#define NANC 9
#define NBOX (M_ROWS*NANC)          /* 147456 */
#define PRE_NMS 6000
#define POST_NMS 300
#define IOU_THR 0.7f
#define REG_OFF (M_ROWS*NANC)            /* 147456 */
#define PROP_OFF (REG_OFF + M_ROWS*NANC*4) /* 737280 */
#define SEL_BLOCKS 288
#define NWORDS 188                      /* ceil(6000/32) */

// ---------------- scratch (device globals; no allocation) ----------------
__device__ float g_h[M_ROWS*N1];            // bottleneck activations (32MB)
__device__ float g_boxes[NBOX*4];           // decoded+clipped boxes
__device__ unsigned long long g_keys[NBOX]; // (score_bits<<32)|~idx
__device__ unsigned long long g_ckeys[PRE_NMS];
__device__ float g_sboxes[PRE_NMS*4];       // boxes in sorted (score-desc) order
__device__ unsigned int g_mask[PRE_NMS*NWORDS]; // pairwise iou>thr bitmask (4.5MB)
__device__ unsigned int g_hist[256];
__device__ unsigned long long g_prefix;
__device__ int g_krem;
__device__ int g_count;
__device__ unsigned int g_bar_count;
__device__ unsigned int g_epoch;

// ================= helpers =================
__device__ __forceinline__ uint32_t smem_u32(const void* p) {
    uint32_t a;
    asm("{ .reg .u64 t; cvta.to.shared.u64 t, %1; cvt.u32.u64 %0, t; }" : "=r"(a) : "l"(p));
    return a;
}
__device__ __forceinline__ void split_tf32(float x, uint32_t& hi, uint32_t& lo) {
    hi = __float_as_uint(x) & 0xFFFFE000u;
    lo = __float_as_uint(x - __uint_as_float(hi));
}
__device__ __forceinline__ void mma_tf32(float* c, const uint32_t* a, uint32_t b0, uint32_t b1) {
    asm volatile(
        "mma.sync.aligned.m16n8k8.row.col.f32.tf32.tf32.f32 "
        "{%0,%1,%2,%3}, {%4,%5,%6,%7}, {%8,%9}, {%0,%1,%2,%3};"
        : "+f"(c[0]), "+f"(c[1]), "+f"(c[2]), "+f"(c[3])
        : "r"(a[0]), "r"(a[1]), "r"(a[2]), "r"(a[3]), "r"(b0), "r"(b1));
}
__device__ __forceinline__ void cp_async16(uint32_t dst, const void* src) {
    asm volatile("cp.async.ca.shared.global [%0], [%1], 16;" :: "r"(dst), "l"(src) : "memory");
}
__device__ __forceinline__ unsigned ld_cg_u32(const unsigned* p) {
    unsigned v;
    asm volatile("ld.global.cg.u32 %0, [%1];" : "=r"(v) : "l"(p) : "memory");
    return v;
}

// ================= kernel 1: split-TF32 warp-MMA bottleneck GEMM =================
#define PADA 36
#define PADB 136
#define A_BUF_BYTES (128*PADA*4)
#define B_BUF_BYTES (32*PADB*4)
#define GEMM_SMEM (2*A_BUF_BYTES + 2*B_BUF_BYTES)

__global__ __launch_bounds__(256, 2)
void gemm_bneck_mma(const float* __restrict__ A, const float* __restrict__ W,
                    const float* __restrict__ bias) {
    extern __shared__ float sm[];
    float* As = sm;
    float* Bs = sm + 2*128*PADA;
    const uint32_t sA = smem_u32(As);
    const uint32_t sB = smem_u32(Bs);

    const int tid = threadIdx.x;
    const int lane = tid & 31;
    const int wid = tid >> 5;
    const int m0 = blockIdx.y * 128;
    const int n0 = blockIdx.x * 128;
    const int mrow = (wid & 3) * 32;
    const int ncol = (wid >> 2) * 64;
    const int quad = lane >> 2;
    const int tq = lane & 3;

    float c[2][8][4];
#pragma unroll
    for (int mt = 0; mt < 2; mt++)
#pragma unroll
        for (int nt = 0; nt < 8; nt++)
#pragma unroll
            for (int j = 0; j < 4; j++) c[mt][nt][j] = 0.f;

    auto prefetch = [&](int s, int buf) {
        const int k0 = s * 32;
#pragma unroll
        for (int i = 0; i < 4; i++) {
            int idx = tid + i * 256;
            int r = idx >> 3, c4 = idx & 7;
            cp_async16(sA + (uint32_t)buf * A_BUF_BYTES + (uint32_t)(r * PADA + c4 * 4) * 4,
                       A + (size_t)(m0 + r) * K1 + k0 + c4 * 4);
        }
#pragma unroll
        for (int i = 0; i < 4; i++) {
            int idx = tid + i * 256;
            int r = idx >> 5, c4 = idx & 31;
            cp_async16(sB + (uint32_t)buf * B_BUF_BYTES + (uint32_t)(r * PADB + c4 * 4) * 4,
                       W + (size_t)(k0 + r) * N1 + n0 + c4 * 4);
        }
        asm volatile("cp.async.commit_group;" ::: "memory");
    };

    prefetch(0, 0);

    for (int s = 0; s < 32; s++) {
        const int buf = s & 1;
        if (s < 31) {
            prefetch(s + 1, buf ^ 1);
            asm volatile("cp.async.wait_group 1;" ::: "memory");
        } else {
            asm volatile("cp.async.wait_group 0;" ::: "memory");
        }
        __syncthreads();

        const float* Ab = As + buf * (128 * PADA);
        const float* Bb = Bs + buf * (32 * PADB);

#pragma unroll
        for (int kk = 0; kk < 4; kk++) {
            uint32_t ah[2][4], al[2][4];
#pragma unroll
            for (int mt = 0; mt < 2; mt++) {
                const int rbase = mrow + mt * 16 + quad;
                const int cbase = kk * 8 + tq;
                float r0 = Ab[(rbase)     * PADA + cbase];
                float r1 = Ab[(rbase + 8) * PADA + cbase];
                float r2 = Ab[(rbase)     * PADA + cbase + 4];
                float r3 = Ab[(rbase + 8) * PADA + cbase + 4];
                split_tf32(r0, ah[mt][0], al[mt][0]);
                split_tf32(r1, ah[mt][1], al[mt][1]);
                split_tf32(r2, ah[mt][2], al[mt][2]);
                split_tf32(r3, ah[mt][3], al[mt][3]);
            }
#pragma unroll
            for (int nt = 0; nt < 8; nt++) {
                const int n = ncol + nt * 8 + quad;
                float b0r = Bb[(kk * 8 + tq)     * PADB + n];
                float b1r = Bb[(kk * 8 + tq + 4) * PADB + n];
                uint32_t bh0, bl0, bh1, bl1;
                split_tf32(b0r, bh0, bl0);
                split_tf32(b1r, bh1, bl1);
#pragma unroll
                for (int mt = 0; mt < 2; mt++) {
                    mma_tf32(c[mt][nt], ah[mt], bh0, bh1);
                    mma_tf32(c[mt][nt], ah[mt], bl0, bl1);
                    mma_tf32(c[mt][nt], al[mt], bh0, bh1);
                }
            }
        }
        __syncthreads();
    }

#pragma unroll
    for (int nt = 0; nt < 8; nt++) {
        const int nc = n0 + ncol + nt * 8 + 2 * tq;
        const float bia0 = __ldg(&bias[nc]);
        const float bia1 = __ldg(&bias[nc + 1]);
#pragma unroll
        for (int mt = 0; mt < 2; mt++) {
            const int row0 = m0 + mrow + mt * 16 + quad;
            float2 v01, v23;
            v01.x = fmaxf(c[mt][nt][0] + bia0, 0.f);
            v01.y = fmaxf(c[mt][nt][1] + bia1, 0.f);
            v23.x = fmaxf(c[mt][nt][2] + bia0, 0.f);
            v23.y = fmaxf(c[mt][nt][3] + bia1, 0.f);
            *(float2*)&g_h[(size_t)row0 * N1 + nc]       = v01;
            *(float2*)&g_h[(size_t)(row0 + 8) * N1 + nc] = v23;
        }
    }
}

// ---------------- kernel 2: head GEMM + sigmoid + box decode ----------------
__global__ __launch_bounds__(256, 4)
void head_kernel(const float* __restrict__ ancs,
                 const float* __restrict__ wc, const float* __restrict__ bc,
                 const float* __restrict__ wr, const float* __restrict__ br,
                 float* __restrict__ out) {
    __shared__ float Hs[32][64];
    __shared__ float Ws[32][48];
    __shared__ float Os[64][48];
    const int tid = threadIdx.x;
    const int tx = tid & 15;
    const int ty = tid >> 4;
    const int gr0 = blockIdx.x * 64;

    if (blockIdx.x == 0 && tid == 0) {
        g_prefix = 0ull;
        g_krem = PRE_NMS;
        g_count = 0;
        g_bar_count = 0u;
        g_epoch = 0u;
    }

    float acc[4][3];
#pragma unroll
    for (int i = 0; i < 4; i++)
#pragma unroll
        for (int j = 0; j < 3; j++) acc[i][j] = 0.f;

    for (int k0 = 0; k0 < N1; k0 += 32) {
#pragma unroll
        for (int v = 0; v < 2; v++) {
            int lin = tid * 8 + v * 4;
            int r = lin >> 5;
            int c = lin & 31;
            float4 h4 = *(const float4*)&g_h[(size_t)(gr0 + r) * N1 + k0 + c];
            Hs[c + 0][r] = h4.x; Hs[c + 1][r] = h4.y;
            Hs[c + 2][r] = h4.z; Hs[c + 3][r] = h4.w;
        }
        for (int idx = tid; idx < 32 * 48; idx += 256) {
            int r = idx / 48, o = idx % 48;
            float v = 0.f;
            if (o < 9)       v = wc[(size_t)(k0 + r) * 9 + o];
            else if (o < 45) v = wr[(size_t)(k0 + r) * 36 + (o - 9)];
            Ws[r][o] = v;
        }
        __syncthreads();
#pragma unroll
        for (int k = 0; k < 32; k++) {
            float a0 = Hs[k][ty * 4 + 0], a1 = Hs[k][ty * 4 + 1];
            float a2 = Hs[k][ty * 4 + 2], a3 = Hs[k][ty * 4 + 3];
            float b0 = Ws[k][tx * 3 + 0], b1 = Ws[k][tx * 3 + 1], b2 = Ws[k][tx * 3 + 2];
            acc[0][0] += a0 * b0; acc[0][1] += a0 * b1; acc[0][2] += a0 * b2;
            acc[1][0] += a1 * b0; acc[1][1] += a1 * b1; acc[1][2] += a1 * b2;
            acc[2][0] += a2 * b0; acc[2][1] += a2 * b1; acc[2][2] += a2 * b2;
            acc[3][0] += a3 * b0; acc[3][1] += a3 * b1; acc[3][2] += a3 * b2;
        }
        __syncthreads();
    }
#pragma unroll
    for (int i = 0; i < 4; i++)
#pragma unroll
        for (int j = 0; j < 3; j++) {
            int o = tx * 3 + j;
            float bia = (o < 9) ? bc[o] : ((o < 45) ? br[o - 9] : 0.f);
            Os[ty * 4 + i][o] = acc[i][j] + bia;
        }
    __syncthreads();
    for (int idx = tid; idx < 64 * 45; idx += 256) {
        int r = idx / 45, o = idx % 45;
        float v = Os[r][o];
        int grow = gr0 + r;
        if (o < 9) out[(size_t)grow * 9 + o] = 1.f / (1.f + expf(-v));
        else       out[REG_OFF + (size_t)grow * 36 + (o - 9)] = v;
    }
    for (int t = tid; t < 64 * 9; t += 256) {
        int r = t / 9, a = t % 9;
        int gi = (gr0 + r) * 9 + a;
        float logit = Os[r][a];
        float score = 1.f / (1.f + expf(-logit));
        float tx_ = Os[r][9 + a * 4 + 0];
        float ty_ = Os[r][9 + a * 4 + 1];
        float tw_ = Os[r][9 + a * 4 + 2];
        float th_ = Os[r][9 + a * 4 + 3];
        float acx = ancs[(size_t)gi * 4 + 0];
        float acy = ancs[(size_t)gi * 4 + 1];
        float aw  = ancs[(size_t)gi * 4 + 2];
        float ah  = ancs[(size_t)gi * 4 + 3];
        float cx = acx + tx_ * aw;
        float cy = acy + ty_ * ah;
        float ww = aw * expf(tw_);
        float hh = ah * expf(th_);
        float x1 = fminf(fmaxf(cx - ww * 0.5f, 0.f), 1.f);
        float y1 = fminf(fmaxf(cy - hh * 0.5f, 0.f), 1.f);
        float x2 = fminf(fmaxf(cx + ww * 0.5f, 0.f), 1.f);
        float y2 = fminf(fmaxf(cy + hh * 0.5f, 0.f), 1.f);
        g_boxes[(size_t)gi * 4 + 0] = x1;
        g_boxes[(size_t)gi * 4 + 1] = y1;
        g_boxes[(size_t)gi * 4 + 2] = x2;
        g_boxes[(size_t)gi * 4 + 3] = y2;
        unsigned sb = __float_as_uint(score);
        g_keys[gi] = ((unsigned long long)sb << 32) | (unsigned long long)(~(unsigned)gi);
    }
}

// ===== selection: exact 64-bit radix select + compact, ONE kernel =====
__global__ __launch_bounds__(256)
void select_all() {
    __shared__ unsigned int sh[256];
    __shared__ unsigned long long s_pref;
    __shared__ int s_last;
    const int tid = threadIdx.x;
    const int gs = gridDim.x * blockDim.x;
    const int gi = blockIdx.x * blockDim.x + tid;
    unsigned myep = 0;

    for (int p = 7; p >= 0; p--) {
        const int shift = p * 8;
        if (tid == 0)
            s_pref = (p == 7) ? 0ull : atomicAdd(&g_prefix, 0ull);
        sh[tid] = 0u;
        __syncthreads();
        const unsigned long long pref = s_pref;
        const unsigned long long mask = (p == 7) ? 0ull : (~0ull << (shift + 8));

        for (int i = gi; i < NBOX; i += gs) {
            unsigned long long k = g_keys[i];
            if (((k ^ pref) & mask) == 0ull)
                atomicAdd(&sh[(unsigned)(k >> shift) & 255u], 1u);
        }
        __syncthreads();
        if (sh[tid]) atomicAdd(&g_hist[tid], sh[tid]);
        __threadfence();
        myep++;

        if (tid == 0)
            s_last = (atomicAdd(&g_bar_count, 1u) == (unsigned)(gridDim.x - 1)) ? 1 : 0;
        __syncthreads();

        if (s_last) {
            sh[tid] = atomicAdd(&g_hist[tid], 0u);
            __syncthreads();
            if (tid == 0) {
                int k = atomicAdd(&g_krem, 0);
                int b = 255;
                for (; b >= 0; --b) {
                    int c = (int)sh[b];
                    if (c >= k) break;
                    k -= c;
                }
                if (b < 0) b = 0;
                atomicOr(&g_prefix, ((unsigned long long)(unsigned)b) << shift);
                atomicExch(&g_krem, k);
            }
            atomicExch(&g_hist[tid], 0u);
            __threadfence();
            __syncthreads();
            if (tid == 0) {
                atomicExch(&g_bar_count, 0u);
                __threadfence();
                atomicAdd(&g_epoch, 1u);
            }
        }
        if (tid == 0) {
            while (ld_cg_u32(&g_epoch) < myep) __nanosleep(64);
        }
        __syncthreads();
    }

    if (tid == 0) s_pref = atomicAdd(&g_prefix, 0ull);
    __syncthreads();
    const unsigned long long thr = s_pref;
    for (int i = gi; i < NBOX; i += gs) {
        unsigned long long k = g_keys[i];
        if (k >= thr) {
            int pos = atomicAdd(&g_count, 1);
            if (pos < PRE_NMS) g_ckeys[pos] = k;
        }
    }
}

// ===== NMS stage 1: parallel rank (keys distinct) + scatter boxes =====
// rank(i) = #{j : key_j > key_i}  -> descending stable order, == argsort(-score)
#define RANK_ROWS 64
__global__ __launch_bounds__(256, 1)
void rank_kernel() {
    extern __shared__ unsigned long long skey[];   // 6000 * 8 = 48000 B
    __shared__ int scnt[RANK_ROWS];
    const int tid = threadIdx.x;
    const int nvalid = min(g_count, PRE_NMS);

    for (int i = tid; i < PRE_NMS; i += 256)
        skey[i] = (i < nvalid) ? g_ckeys[i] : 0ull;
    if (tid < RANK_ROWS) scnt[tid] = 0;
    __syncthreads();

    const int i0 = blockIdx.x * RANK_ROWS;
    // 4 threads per element, each scans a quarter of the key set
    const int e = tid >> 2;          // 0..63
    const int q = tid & 3;
    const int i = i0 + e;
    if (i < nvalid) {
        const unsigned long long ki = skey[i];
        const int j0 = q * (PRE_NMS / 4);
        const int j1 = (q == 3) ? PRE_NMS : j0 + (PRE_NMS / 4);
        int cnt = 0;
        for (int j = j0; j < j1; j++)
            cnt += (skey[j] > ki) ? 1 : 0;
        atomicAdd(&scnt[e], cnt);
    }
    __syncthreads();
    if (tid < RANK_ROWS) {
        const int ii = i0 + tid;
        if (ii < nvalid) {
            const int r = scnt[tid];
            const unsigned gidx = ~(unsigned)skey[ii];
            float4 b = *(const float4*)&g_boxes[(size_t)gidx * 4];
            *(float4*)&g_sboxes[(size_t)r * 4] = b;
        }
    }
}

// ===== NMS stage 2: pairwise IoU bitmask (no divisions on the hot path) =====
#define MASK_ROWS 64
__global__ __launch_bounds__(256, 1)
void mask_kernel() {
    extern __shared__ float4 sbox[];   // 6000 * 16 = 96000 B
    const int tid = threadIdx.x;
    for (int i = tid; i < PRE_NMS; i += 256)
        sbox[i] = *(const float4*)&g_sboxes[(size_t)i * 4];
    __syncthreads();

    const int i0 = blockIdx.x * MASK_ROWS;
    for (int p = tid; p < MASK_ROWS * NWORDS; p += 256) {
        const int li = p / NWORDS;
        const int w = p % NWORDS;
        const int i = i0 + li;
        if (i >= PRE_NMS) break;
        const float4 bi = sbox[i];
        const float ai = (bi.z - bi.x) * (bi.w - bi.y);
        unsigned m = 0u;
        const int jbase = w * 32;
        const int jmax = min(32, PRE_NMS - jbase);
#pragma unroll 4
        for (int jj = 0; jj < jmax; jj++) {
            const float4 bj = sbox[jbase + jj];
            float iw = fminf(bi.z, bj.z) - fmaxf(bi.x, bj.x);
            float ih = fminf(bi.w, bj.w) - fmaxf(bi.y, bj.y);
            iw = fmaxf(iw, 0.f);
            ih = fmaxf(ih, 0.f);
            const float inter = iw * ih;
            const float aj = (bj.z - bj.x) * (bj.w - bj.y);
            const float uni = ai + aj - inter;
            // margin test: avoid division except in the ~1e-4 ambiguity band
            const float pthr = IOU_THR * uni;
            bool sup;
            if (inter > pthr * 1.0001f)      sup = true;
            else if (inter < pthr * 0.9999f) sup = false;
            else {
                const float iou = (uni > 0.f) ? inter / uni : 0.f;
                sup = (iou > IOU_THR);
            }
            if (sup) m |= (1u << jj);
        }
        g_mask[(size_t)i * NWORDS + w] = m;
    }
}

// ===== NMS stage 3: greedy scan over bitmask (only serial part) =====
__global__ __launch_bounds__(256, 1)
void scan_kernel(float* __restrict__ out) {
    __shared__ unsigned removed[NWORDS];
    __shared__ int s_win;
    const int tid = threadIdx.x;
    const int nvalid = min(g_count, PRE_NMS);

    if (tid < NWORDS) {
        unsigned init = 0u;
        int base = tid * 32;
        if (base + 32 > nvalid) {
            for (int b = 0; b < 32; b++)
                if (base + b >= nvalid) init |= (1u << b);
        }
        removed[tid] = init;
    }
    __syncthreads();

    int cw = 0;
    int done_at = POST_NMS;
    for (int it = 0; it < POST_NMS; it++) {
        if (tid == 0) {
            int win = -1;
            for (; cw < NWORDS; cw++) {
                unsigned u = ~removed[cw];
                if (u) { win = cw * 32 + (__ffs(u) - 1); break; }
            }
            s_win = win;
        }
        __syncthreads();
        const int i = s_win;
        if (i < 0) { done_at = it; break; }
        if (tid == 0) {
            float4 b = *(const float4*)&g_sboxes[(size_t)i * 4];
            out[PROP_OFF + it * 4 + 0] = b.x;
            out[PROP_OFF + it * 4 + 1] = b.y;
            out[PROP_OFF + it * 4 + 2] = b.z;
            out[PROP_OFF + it * 4 + 3] = b.w;
        }
        if (tid < NWORDS)
            removed[tid] |= g_mask[(size_t)i * NWORDS + tid];   // self-bit is set (iou=1)
        __syncthreads();
    }
    for (int idx = done_at * 4 + tid; idx < POST_NMS * 4; idx += 256)
        out[PROP_OFF + idx] = 0.f;
}

// ---------------- launcher ----------------
extern "C" void kernel_launch(void* const* d_in, const int* in_sizes, int n_in,
                              void* d_out, int out_size) {
    const float* feats   = (const float*)d_in[0];
    const float* ancs    = (const float*)d_in[1];
    const float* w_bneck = (const float*)d_in[3];
    const float* b_bneck = (const float*)d_in[4];
    const float* w_cls   = (const float*)d_in[5];
    const float* b_cls   = (const float*)d_in[6];
    const float* w_reg   = (const float*)d_in[7];
    const float* b_reg   = (const float*)d_in[8];
    float* out = (float*)d_out;

    cudaFuncSetAttribute(gemm_bneck_mma, cudaFuncAttributeMaxDynamicSharedMemorySize, GEMM_SMEM);
    cudaFuncSetAttribute(rank_kernel, cudaFuncAttributeMaxDynamicSharedMemorySize, PRE_NMS * 8);
    cudaFuncSetAttribute(mask_kernel, cudaFuncAttributeMaxDynamicSharedMemorySize, PRE_NMS * 16);

    gemm_bneck_mma<<<dim3(4, 128), 256, GEMM_SMEM>>>(feats, w_bneck, b_bneck);
    head_kernel<<<M_ROWS / 64, 256>>>(ancs, w_cls, b_cls, w_reg, b_reg, out);
    select_all<<<SEL_BLOCKS, 256>>>();
    rank_kernel<<<(PRE_NMS + RANK_ROWS - 1) / RANK_ROWS, 256, PRE_NMS * 8>>>();
    mask_kernel<<<(PRE_NMS + MASK_ROWS - 1) / MASK_ROWS, 256, PRE_NMS * 16>>>();
    scan_kernel<<<1, 256>>>(out);
}

// round 8
// speedup vs baseline: 1.3060x; 1.0311x over previous
#include <cuda_runtime.h>
#include <math.h>
#include <stdint.h>

#define M_ROWS 16384
#define K1 1024
#define N1 512
#define NANC 9
#define NBOX (M_ROWS*NANC)          /* 147456 */
#define PRE_NMS 6000
#define POST_NMS 300
#define IOU_THR 0.7f
#define REG_OFF (M_ROWS*NANC)            /* 147456 */
#define PROP_OFF (REG_OFF + M_ROWS*NANC*4) /* 737280 */
#define SEL_BLOCKS 288
#define NWORDS 188                      /* ceil(6000/32) */

// ---------------- scratch (device globals; no allocation) ----------------
__device__ float g_h[M_ROWS*N1];            // bottleneck activations (32MB)
__device__ float g_boxes[NBOX*4];           // decoded+clipped boxes
__device__ unsigned long long g_keys[NBOX]; // (score_bits<<32)|~idx
__device__ unsigned long long g_ckeys[PRE_NMS];
__device__ float g_sboxes[PRE_NMS*4];       // boxes in sorted (score-desc) order
__device__ unsigned int g_mask[PRE_NMS*NWORDS]; // pairwise iou>thr bitmask (4.5MB)
__device__ unsigned int g_hist[256];
__device__ unsigned long long g_prefix;
__device__ int g_krem;
__device__ int g_count;
__device__ unsigned int g_bar_count;
__device__ unsigned int g_epoch;

// ================= helpers =================
__device__ __forceinline__ uint32_t smem_u32(const void* p) {
    uint32_t a;
    asm("{ .reg .u64 t; cvta.to.shared.u64 t, %1; cvt.u32.u64 %0, t; }" : "=r"(a) : "l"(p));
    return a;
}
__device__ __forceinline__ void split_tf32(float x, uint32_t& hi, uint32_t& lo) {
    hi = __float_as_uint(x) & 0xFFFFE000u;
    lo = __float_as_uint(x - __uint_as_float(hi));
}
__device__ __forceinline__ void mma_tf32(float* c, const uint32_t* a, uint32_t b0, uint32_t b1) {
    asm volatile(
        "mma.sync.aligned.m16n8k8.row.col.f32.tf32.tf32.f32 "
        "{%0,%1,%2,%3}, {%4,%5,%6,%7}, {%8,%9}, {%0,%1,%2,%3};"
        : "+f"(c[0]), "+f"(c[1]), "+f"(c[2]), "+f"(c[3])
        : "r"(a[0]), "r"(a[1]), "r"(a[2]), "r"(a[3]), "r"(b0), "r"(b1));
}
__device__ __forceinline__ void cp_async16(uint32_t dst, const void* src) {
    asm volatile("cp.async.ca.shared.global [%0], [%1], 16;" :: "r"(dst), "l"(src) : "memory");
}
__device__ __forceinline__ unsigned ld_cg_u32(const unsigned* p) {
    unsigned v;
    asm volatile("ld.global.cg.u32 %0, [%1];" : "=r"(v) : "l"(p) : "memory");
    return v;
}

// ================= kernel 1: split-TF32 warp-MMA bottleneck GEMM =================
#define PADA 36
#define PADB 136
#define A_BUF_BYTES (128*PADA*4)
#define B_BUF_BYTES (32*PADB*4)
#define GEMM_SMEM (2*A_BUF_BYTES + 2*B_BUF_BYTES)

__global__ __launch_bounds__(256, 2)
void gemm_bneck_mma(const float* __restrict__ A, const float* __restrict__ W,
                    const float* __restrict__ bias) {
    extern __shared__ float sm[];
    float* As = sm;
    float* Bs = sm + 2*128*PADA;
    const uint32_t sA = smem_u32(As);
    const uint32_t sB = smem_u32(Bs);

    const int tid = threadIdx.x;
    const int lane = tid & 31;
    const int wid = tid >> 5;
    const int m0 = blockIdx.y * 128;
    const int n0 = blockIdx.x * 128;
    const int mrow = (wid & 3) * 32;
    const int ncol = (wid >> 2) * 64;
    const int quad = lane >> 2;
    const int tq = lane & 3;

    float c[2][8][4];
#pragma unroll
    for (int mt = 0; mt < 2; mt++)
#pragma unroll
        for (int nt = 0; nt < 8; nt++)
#pragma unroll
            for (int j = 0; j < 4; j++) c[mt][nt][j] = 0.f;

    auto prefetch = [&](int s, int buf) {
        const int k0 = s * 32;
#pragma unroll
        for (int i = 0; i < 4; i++) {
            int idx = tid + i * 256;
            int r = idx >> 3, c4 = idx & 7;
            cp_async16(sA + (uint32_t)buf * A_BUF_BYTES + (uint32_t)(r * PADA + c4 * 4) * 4,
                       A + (size_t)(m0 + r) * K1 + k0 + c4 * 4);
        }
#pragma unroll
        for (int i = 0; i < 4; i++) {
            int idx = tid + i * 256;
            int r = idx >> 5, c4 = idx & 31;
            cp_async16(sB + (uint32_t)buf * B_BUF_BYTES + (uint32_t)(r * PADB + c4 * 4) * 4,
                       W + (size_t)(k0 + r) * N1 + n0 + c4 * 4);
        }
        asm volatile("cp.async.commit_group;" ::: "memory");
    };

    prefetch(0, 0);

    for (int s = 0; s < 32; s++) {
        const int buf = s & 1;
        if (s < 31) {
            prefetch(s + 1, buf ^ 1);
            asm volatile("cp.async.wait_group 1;" ::: "memory");
        } else {
            asm volatile("cp.async.wait_group 0;" ::: "memory");
        }
        __syncthreads();

        const float* Ab = As + buf * (128 * PADA);
        const float* Bb = Bs + buf * (32 * PADB);

#pragma unroll
        for (int kk = 0; kk < 4; kk++) {
            uint32_t ah[2][4], al[2][4];
#pragma unroll
            for (int mt = 0; mt < 2; mt++) {
                const int rbase = mrow + mt * 16 + quad;
                const int cbase = kk * 8 + tq;
                float r0 = Ab[(rbase)     * PADA + cbase];
                float r1 = Ab[(rbase + 8) * PADA + cbase];
                float r2 = Ab[(rbase)     * PADA + cbase + 4];
                float r3 = Ab[(rbase + 8) * PADA + cbase + 4];
                split_tf32(r0, ah[mt][0], al[mt][0]);
                split_tf32(r1, ah[mt][1], al[mt][1]);
                split_tf32(r2, ah[mt][2], al[mt][2]);
                split_tf32(r3, ah[mt][3], al[mt][3]);
            }
#pragma unroll
            for (int nt = 0; nt < 8; nt++) {
                const int n = ncol + nt * 8 + quad;
                float b0r = Bb[(kk * 8 + tq)     * PADB + n];
                float b1r = Bb[(kk * 8 + tq + 4) * PADB + n];
                uint32_t bh0, bl0, bh1, bl1;
                split_tf32(b0r, bh0, bl0);
                split_tf32(b1r, bh1, bl1);
#pragma unroll
                for (int mt = 0; mt < 2; mt++) {
                    mma_tf32(c[mt][nt], ah[mt], bh0, bh1);
                    mma_tf32(c[mt][nt], ah[mt], bl0, bl1);
                    mma_tf32(c[mt][nt], al[mt], bh0, bh1);
                }
            }
        }
        __syncthreads();
    }

#pragma unroll
    for (int nt = 0; nt < 8; nt++) {
        const int nc = n0 + ncol + nt * 8 + 2 * tq;
        const float bia0 = __ldg(&bias[nc]);
        const float bia1 = __ldg(&bias[nc + 1]);
#pragma unroll
        for (int mt = 0; mt < 2; mt++) {
            const int row0 = m0 + mrow + mt * 16 + quad;
            float2 v01, v23;
            v01.x = fmaxf(c[mt][nt][0] + bia0, 0.f);
            v01.y = fmaxf(c[mt][nt][1] + bia1, 0.f);
            v23.x = fmaxf(c[mt][nt][2] + bia0, 0.f);
            v23.y = fmaxf(c[mt][nt][3] + bia1, 0.f);
            *(float2*)&g_h[(size_t)row0 * N1 + nc]       = v01;
            *(float2*)&g_h[(size_t)(row0 + 8) * N1 + nc] = v23;
        }
    }
}

// ---------------- kernel 2: head GEMM + sigmoid + box decode ----------------
__global__ __launch_bounds__(256, 4)
void head_kernel(const float* __restrict__ ancs,
                 const float* __restrict__ wc, const float* __restrict__ bc,
                 const float* __restrict__ wr, const float* __restrict__ br,
                 float* __restrict__ out) {
    __shared__ float Hs[32][64];
    __shared__ float Ws[32][48];
    __shared__ float Os[64][48];
    const int tid = threadIdx.x;
    const int tx = tid & 15;
    const int ty = tid >> 4;
    const int gr0 = blockIdx.x * 64;

    if (blockIdx.x == 0 && tid == 0) {
        g_prefix = 0ull;
        g_krem = PRE_NMS;
        g_count = 0;
        g_bar_count = 0u;
        g_epoch = 0u;
    }

    float acc[4][3];
#pragma unroll
    for (int i = 0; i < 4; i++)
#pragma unroll
        for (int j = 0; j < 3; j++) acc[i][j] = 0.f;

    for (int k0 = 0; k0 < N1; k0 += 32) {
#pragma unroll
        for (int v = 0; v < 2; v++) {
            int lin = tid * 8 + v * 4;
            int r = lin >> 5;
            int c = lin & 31;
            float4 h4 = *(const float4*)&g_h[(size_t)(gr0 + r) * N1 + k0 + c];
            Hs[c + 0][r] = h4.x; Hs[c + 1][r] = h4.y;
            Hs[c + 2][r] = h4.z; Hs[c + 3][r] = h4.w;
        }
        for (int idx = tid; idx < 32 * 48; idx += 256) {
            int r = idx / 48, o = idx % 48;
            float v = 0.f;
            if (o < 9)       v = wc[(size_t)(k0 + r) * 9 + o];
            else if (o < 45) v = wr[(size_t)(k0 + r) * 36 + (o - 9)];
            Ws[r][o] = v;
        }
        __syncthreads();
#pragma unroll
        for (int k = 0; k < 32; k++) {
            float a0 = Hs[k][ty * 4 + 0], a1 = Hs[k][ty * 4 + 1];
            float a2 = Hs[k][ty * 4 + 2], a3 = Hs[k][ty * 4 + 3];
            float b0 = Ws[k][tx * 3 + 0], b1 = Ws[k][tx * 3 + 1], b2 = Ws[k][tx * 3 + 2];
            acc[0][0] += a0 * b0; acc[0][1] += a0 * b1; acc[0][2] += a0 * b2;
            acc[1][0] += a1 * b0; acc[1][1] += a1 * b1; acc[1][2] += a1 * b2;
            acc[2][0] += a2 * b0; acc[2][1] += a2 * b1; acc[2][2] += a2 * b2;
            acc[3][0] += a3 * b0; acc[3][1] += a3 * b1; acc[3][2] += a3 * b2;
        }
        __syncthreads();
    }
#pragma unroll
    for (int i = 0; i < 4; i++)
#pragma unroll
        for (int j = 0; j < 3; j++) {
            int o = tx * 3 + j;
            float bia = (o < 9) ? bc[o] : ((o < 45) ? br[o - 9] : 0.f);
            Os[ty * 4 + i][o] = acc[i][j] + bia;
        }
    __syncthreads();
    for (int idx = tid; idx < 64 * 45; idx += 256) {
        int r = idx / 45, o = idx % 45;
        float v = Os[r][o];
        int grow = gr0 + r;
        if (o < 9) out[(size_t)grow * 9 + o] = 1.f / (1.f + expf(-v));
        else       out[REG_OFF + (size_t)grow * 36 + (o - 9)] = v;
    }
    for (int t = tid; t < 64 * 9; t += 256) {
        int r = t / 9, a = t % 9;
        int gi = (gr0 + r) * 9 + a;
        float logit = Os[r][a];
        float score = 1.f / (1.f + expf(-logit));
        float tx_ = Os[r][9 + a * 4 + 0];
        float ty_ = Os[r][9 + a * 4 + 1];
        float tw_ = Os[r][9 + a * 4 + 2];
        float th_ = Os[r][9 + a * 4 + 3];
        float acx = ancs[(size_t)gi * 4 + 0];
        float acy = ancs[(size_t)gi * 4 + 1];
        float aw  = ancs[(size_t)gi * 4 + 2];
        float ah  = ancs[(size_t)gi * 4 + 3];
        float cx = acx + tx_ * aw;
        float cy = acy + ty_ * ah;
        float ww = aw * expf(tw_);
        float hh = ah * expf(th_);
        float x1 = fminf(fmaxf(cx - ww * 0.5f, 0.f), 1.f);
        float y1 = fminf(fmaxf(cy - hh * 0.5f, 0.f), 1.f);
        float x2 = fminf(fmaxf(cx + ww * 0.5f, 0.f), 1.f);
        float y2 = fminf(fmaxf(cy + hh * 0.5f, 0.f), 1.f);
        g_boxes[(size_t)gi * 4 + 0] = x1;
        g_boxes[(size_t)gi * 4 + 1] = y1;
        g_boxes[(size_t)gi * 4 + 2] = x2;
        g_boxes[(size_t)gi * 4 + 3] = y2;
        unsigned sb = __float_as_uint(score);
        g_keys[gi] = ((unsigned long long)sb << 32) | (unsigned long long)(~(unsigned)gi);
    }
}

// ===== selection: exact 64-bit radix select + compact, ONE kernel =====
__global__ __launch_bounds__(256)
void select_all() {
    __shared__ unsigned int sh[256];
    __shared__ unsigned long long s_pref;
    __shared__ int s_last;
    const int tid = threadIdx.x;
    const int gs = gridDim.x * blockDim.x;
    const int gi = blockIdx.x * blockDim.x + tid;
    unsigned myep = 0;

    for (int p = 7; p >= 0; p--) {
        const int shift = p * 8;
        if (tid == 0)
            s_pref = (p == 7) ? 0ull : atomicAdd(&g_prefix, 0ull);
        sh[tid] = 0u;
        __syncthreads();
        const unsigned long long pref = s_pref;
        const unsigned long long mask = (p == 7) ? 0ull : (~0ull << (shift + 8));

        for (int i = gi; i < NBOX; i += gs) {
            unsigned long long k = g_keys[i];
            if (((k ^ pref) & mask) == 0ull)
                atomicAdd(&sh[(unsigned)(k >> shift) & 255u], 1u);
        }
        __syncthreads();
        if (sh[tid]) atomicAdd(&g_hist[tid], sh[tid]);
        __threadfence();
        myep++;

        if (tid == 0)
            s_last = (atomicAdd(&g_bar_count, 1u) == (unsigned)(gridDim.x - 1)) ? 1 : 0;
        __syncthreads();

        if (s_last) {
            sh[tid] = atomicAdd(&g_hist[tid], 0u);
            __syncthreads();
            if (tid == 0) {
                int k = atomicAdd(&g_krem, 0);
                int b = 255;
                for (; b >= 0; --b) {
                    int c = (int)sh[b];
                    if (c >= k) break;
                    k -= c;
                }
                if (b < 0) b = 0;
                atomicOr(&g_prefix, ((unsigned long long)(unsigned)b) << shift);
                atomicExch(&g_krem, k);
            }
            atomicExch(&g_hist[tid], 0u);
            __threadfence();
            __syncthreads();
            if (tid == 0) {
                atomicExch(&g_bar_count, 0u);
                __threadfence();
                atomicAdd(&g_epoch, 1u);
            }
        }
        if (tid == 0) {
            while (ld_cg_u32(&g_epoch) < myep) __nanosleep(64);
        }
        __syncthreads();
    }

    if (tid == 0) s_pref = atomicAdd(&g_prefix, 0ull);
    __syncthreads();
    const unsigned long long thr = s_pref;
    for (int i = gi; i < NBOX; i += gs) {
        unsigned long long k = g_keys[i];
        if (k >= thr) {
            int pos = atomicAdd(&g_count, 1);
            if (pos < PRE_NMS) g_ckeys[pos] = k;
        }
    }
}

// ===== NMS stage 1: parallel rank (keys distinct) + scatter boxes =====
// rank(i) = #{j : key_j > key_i}  -> descending stable order, == argsort(-score)
#define RANK_ROWS 32
__global__ __launch_bounds__(256, 1)
void rank_kernel() {
    extern __shared__ unsigned long long skey[];   // 6000 * 8 = 48000 B
    __shared__ int scnt[RANK_ROWS];
    const int tid = threadIdx.x;
    const int nvalid = min(g_count, PRE_NMS);

    for (int i = tid; i < PRE_NMS; i += 256)
        skey[i] = (i < nvalid) ? g_ckeys[i] : 0ull;
    if (tid < RANK_ROWS) scnt[tid] = 0;
    __syncthreads();

    const int i0 = blockIdx.x * RANK_ROWS;
    // 8 threads per element, each scans an eighth of the key set
    const int e = tid >> 3;          // 0..31
    const int q = tid & 7;
    const int i = i0 + e;
    if (i < nvalid) {
        const unsigned long long ki = skey[i];
        const int j0 = q * (PRE_NMS / 8);
        const int j1 = (q == 7) ? PRE_NMS : j0 + (PRE_NMS / 8);
        int cnt = 0;
        for (int j = j0; j < j1; j++)
            cnt += (skey[j] > ki) ? 1 : 0;
        atomicAdd(&scnt[e], cnt);
    }
    __syncthreads();
    if (tid < RANK_ROWS) {
        const int ii = i0 + tid;
        if (ii < nvalid) {
            const int r = scnt[tid];
            const unsigned gidx = ~(unsigned)skey[ii];
            float4 b = *(const float4*)&g_boxes[(size_t)gidx * 4];
            *(float4*)&g_sboxes[(size_t)r * 4] = b;
        }
    }
}

// ===== NMS stage 2: pairwise IoU bitmask (no divisions on the hot path) =====
#define MASK_ROWS 32
__global__ __launch_bounds__(256, 1)
void mask_kernel() {
    extern __shared__ float4 sbox[];   // 6000 * 16 = 96000 B
    const int tid = threadIdx.x;
    for (int i = tid; i < PRE_NMS; i += 256)
        sbox[i] = *(const float4*)&g_sboxes[(size_t)i * 4];
    __syncthreads();

    const int i0 = blockIdx.x * MASK_ROWS;
    for (int p = tid; p < MASK_ROWS * NWORDS; p += 256) {
        const int li = p / NWORDS;
        const int w = p % NWORDS;
        const int i = i0 + li;
        if (i >= PRE_NMS) break;
        const float4 bi = sbox[i];
        const float ai = (bi.z - bi.x) * (bi.w - bi.y);
        unsigned m = 0u;
        const int jbase = w * 32;
        const int jmax = min(32, PRE_NMS - jbase);
#pragma unroll 4
        for (int jj = 0; jj < jmax; jj++) {
            const float4 bj = sbox[jbase + jj];
            float iw = fminf(bi.z, bj.z) - fmaxf(bi.x, bj.x);
            float ih = fminf(bi.w, bj.w) - fmaxf(bi.y, bj.y);
            iw = fmaxf(iw, 0.f);
            ih = fmaxf(ih, 0.f);
            const float inter = iw * ih;
            const float aj = (bj.z - bj.x) * (bj.w - bj.y);
            const float uni = ai + aj - inter;
            // margin test: avoid division except in the ~1e-4 ambiguity band
            const float pthr = IOU_THR * uni;
            bool sup;
            if (inter > pthr * 1.0001f)      sup = true;
            else if (inter < pthr * 0.9999f) sup = false;
            else {
                const float iou = (uni > 0.f) ? inter / uni : 0.f;
                sup = (iou > IOU_THR);
            }
            if (sup) m |= (1u << jj);
        }
        g_mask[(size_t)i * NWORDS + w] = m;
    }
}

// ===== NMS stage 3: greedy scan, single warp, bitmap in registers =====
#define SCAN_WPL 6   /* words per lane: 6*32 = 192 >= NWORDS */
__global__ __launch_bounds__(32, 1)
void scan_kernel(float* __restrict__ out) {
    const int lane = threadIdx.x;
    const int nvalid = min(g_count, PRE_NMS);

    unsigned rem[SCAN_WPL];
#pragma unroll
    for (int t = 0; t < SCAN_WPL; t++) {
        const int w = lane + 32 * t;
        unsigned v = 0xFFFFFFFFu;
        if (w < NWORDS) {
            v = 0u;
            const int base = w * 32;
            if (base + 32 > nvalid) {
                for (int b = 0; b < 32; b++)
                    if (base + b >= nvalid) v |= (1u << b);
            }
        }
        rem[t] = v;
    }

    int it = 0;
    for (; it < POST_NMS; it++) {
        // per-lane first-alive bit (lane's words are w = lane + 32t, t ascending)
        int cand = 0x7FFFFFFF;
#pragma unroll
        for (int t = 0; t < SCAN_WPL; t++) {
            const unsigned u = ~rem[t];
            if (u != 0u && cand == 0x7FFFFFFF)
                cand = (lane + 32 * t) * 32 + (__ffs(u) - 1);
        }
        // warp-wide min -> winner index known to all lanes
#pragma unroll
        for (int off = 16; off > 0; off >>= 1) {
            const int o = __shfl_xor_sync(0xffffffffu, cand, off);
            cand = min(cand, o);
        }
        const int win = cand;
        if (win == 0x7FFFFFFF) break;

        // output winner box (4 lanes in parallel, overlaps with the row load)
        if (lane < 4)
            out[PROP_OFF + it * 4 + lane] = g_sboxes[(size_t)win * 4 + lane];

        // OR winner's mask row into the register bitmap (6 independent coalesced LDGs)
        const unsigned* row = g_mask + (size_t)win * NWORDS;
#pragma unroll
        for (int t = 0; t < SCAN_WPL; t++) {
            const int w = lane + 32 * t;
            if (w < NWORDS) {
                unsigned m = row[w];
                if (w == (win >> 5)) m |= (1u << (win & 31));   // explicit winner clear
                rem[t] |= m;
            }
        }
    }
    // zero-fill remaining outputs
    for (int idx = it * 4 + lane; idx < POST_NMS * 4; idx += 32)
        out[PROP_OFF + idx] = 0.f;
}

// ---------------- launcher ----------------
extern "C" void kernel_launch(void* const* d_in, const int* in_sizes, int n_in,
                              void* d_out, int out_size) {
    const float* feats   = (const float*)d_in[0];
    const float* ancs    = (const float*)d_in[1];
    const float* w_bneck = (const float*)d_in[3];
    const float* b_bneck = (const float*)d_in[4];
    const float* w_cls   = (const float*)d_in[5];
    const float* b_cls   = (const float*)d_in[6];
    const float* w_reg   = (const float*)d_in[7];
    const float* b_reg   = (const float*)d_in[8];
    float* out = (float*)d_out;

    cudaFuncSetAttribute(gemm_bneck_mma, cudaFuncAttributeMaxDynamicSharedMemorySize, GEMM_SMEM);
    cudaFuncSetAttribute(rank_kernel, cudaFuncAttributeMaxDynamicSharedMemorySize, PRE_NMS * 8);
    cudaFuncSetAttribute(mask_kernel, cudaFuncAttributeMaxDynamicSharedMemorySize, PRE_NMS * 16);

    gemm_bneck_mma<<<dim3(4, 128), 256, GEMM_SMEM>>>(feats, w_bneck, b_bneck);
    head_kernel<<<M_ROWS / 64, 256>>>(ancs, w_cls, b_cls, w_reg, b_reg, out);
    select_all<<<SEL_BLOCKS, 256>>>();
    rank_kernel<<<(PRE_NMS + RANK_ROWS - 1) / RANK_ROWS, 256, PRE_NMS * 8>>>();
    mask_kernel<<<(PRE_NMS + MASK_ROWS - 1) / MASK_ROWS, 256, PRE_NMS * 16>>>();
    scan_kernel<<<1, 32>>>(out);
}

// round 9
// speedup vs baseline: 1.3127x; 1.0051x over previous
#include <cuda_runtime.h>
#include <math.h>
#include <stdint.h>

#define M_ROWS 16384
#define K1 1024
#define N1 512
#define NANC 9
#define NBOX (M_ROWS*NANC)          /* 147456 */
#define PRE_NMS 6000
#define POST_NMS 300
#define IOU_THR 0.7f
#define REG_OFF (M_ROWS*NANC)            /* 147456 */
#define PROP_OFF (REG_OFF + M_ROWS*NANC*4) /* 737280 */
#define SEL_BLOCKS 288
#define NWORDS 188                      /* ceil(6000/32) */

// ---------------- scratch (device globals; no allocation) ----------------
__device__ float g_h[M_ROWS*N1];            // bottleneck activations (32MB)
__device__ float g_boxes[NBOX*4];           // decoded+clipped boxes
__device__ unsigned long long g_keys[NBOX]; // (score_bits<<32)|~idx
__device__ unsigned long long g_ckeys[PRE_NMS];
__device__ float g_sboxes[PRE_NMS*4];       // boxes in sorted (score-desc) order
__device__ unsigned int g_mask[PRE_NMS*NWORDS]; // pairwise iou>thr bitmask (4.5MB)
__device__ unsigned int g_hist[256];
__device__ unsigned long long g_prefix;
__device__ int g_krem;
__device__ int g_count;
__device__ unsigned int g_bar_count;
__device__ unsigned int g_epoch;

// ================= helpers =================
__device__ __forceinline__ uint32_t smem_u32(const void* p) {
    uint32_t a;
    asm("{ .reg .u64 t; cvta.to.shared.u64 t, %1; cvt.u32.u64 %0, t; }" : "=r"(a) : "l"(p));
    return a;
}
__device__ __forceinline__ void split_tf32(float x, uint32_t& hi, uint32_t& lo) {
    hi = __float_as_uint(x) & 0xFFFFE000u;
    lo = __float_as_uint(x - __uint_as_float(hi));
}
__device__ __forceinline__ void mma_tf32(float* c, const uint32_t* a, uint32_t b0, uint32_t b1) {
    asm volatile(
        "mma.sync.aligned.m16n8k8.row.col.f32.tf32.tf32.f32 "
        "{%0,%1,%2,%3}, {%4,%5,%6,%7}, {%8,%9}, {%0,%1,%2,%3};"
        : "+f"(c[0]), "+f"(c[1]), "+f"(c[2]), "+f"(c[3])
        : "r"(a[0]), "r"(a[1]), "r"(a[2]), "r"(a[3]), "r"(b0), "r"(b1));
}
__device__ __forceinline__ void cp_async16(uint32_t dst, const void* src) {
    asm volatile("cp.async.ca.shared.global [%0], [%1], 16;" :: "r"(dst), "l"(src) : "memory");
}
__device__ __forceinline__ unsigned ld_cg_u32(const unsigned* p) {
    unsigned v;
    asm volatile("ld.global.cg.u32 %0, [%1];" : "=r"(v) : "l"(p) : "memory");
    return v;
}

// ================= kernel 1: split-TF32 warp-MMA bottleneck GEMM =================
#define PADA 36
#define PADB 136
#define A_BUF_BYTES (128*PADA*4)
#define B_BUF_BYTES (32*PADB*4)
#define GEMM_SMEM (2*A_BUF_BYTES + 2*B_BUF_BYTES)

__global__ __launch_bounds__(256, 2)
void gemm_bneck_mma(const float* __restrict__ A, const float* __restrict__ W,
                    const float* __restrict__ bias) {
    extern __shared__ float sm[];
    float* As = sm;
    float* Bs = sm + 2*128*PADA;
    const uint32_t sA = smem_u32(As);
    const uint32_t sB = smem_u32(Bs);

    const int tid = threadIdx.x;
    const int lane = tid & 31;
    const int wid = tid >> 5;
    const int m0 = blockIdx.y * 128;
    const int n0 = blockIdx.x * 128;
    const int mrow = (wid & 3) * 32;
    const int ncol = (wid >> 2) * 64;
    const int quad = lane >> 2;
    const int tq = lane & 3;

    float c[2][8][4];
#pragma unroll
    for (int mt = 0; mt < 2; mt++)
#pragma unroll
        for (int nt = 0; nt < 8; nt++)
#pragma unroll
            for (int j = 0; j < 4; j++) c[mt][nt][j] = 0.f;

    auto prefetch = [&](int s, int buf) {
        const int k0 = s * 32;
#pragma unroll
        for (int i = 0; i < 4; i++) {
            int idx = tid + i * 256;
            int r = idx >> 3, c4 = idx & 7;
            cp_async16(sA + (uint32_t)buf * A_BUF_BYTES + (uint32_t)(r * PADA + c4 * 4) * 4,
                       A + (size_t)(m0 + r) * K1 + k0 + c4 * 4);
        }
#pragma unroll
        for (int i = 0; i < 4; i++) {
            int idx = tid + i * 256;
            int r = idx >> 5, c4 = idx & 31;
            cp_async16(sB + (uint32_t)buf * B_BUF_BYTES + (uint32_t)(r * PADB + c4 * 4) * 4,
                       W + (size_t)(k0 + r) * N1 + n0 + c4 * 4);
        }
        asm volatile("cp.async.commit_group;" ::: "memory");
    };

    prefetch(0, 0);

    for (int s = 0; s < 32; s++) {
        const int buf = s & 1;
        if (s < 31) {
            prefetch(s + 1, buf ^ 1);
            asm volatile("cp.async.wait_group 1;" ::: "memory");
        } else {
            asm volatile("cp.async.wait_group 0;" ::: "memory");
        }
        __syncthreads();

        const float* Ab = As + buf * (128 * PADA);
        const float* Bb = Bs + buf * (32 * PADB);

#pragma unroll
        for (int kk = 0; kk < 4; kk++) {
            uint32_t ah[2][4], al[2][4];
#pragma unroll
            for (int mt = 0; mt < 2; mt++) {
                const int rbase = mrow + mt * 16 + quad;
                const int cbase = kk * 8 + tq;
                float r0 = Ab[(rbase)     * PADA + cbase];
                float r1 = Ab[(rbase + 8) * PADA + cbase];
                float r2 = Ab[(rbase)     * PADA + cbase + 4];
                float r3 = Ab[(rbase + 8) * PADA + cbase + 4];
                split_tf32(r0, ah[mt][0], al[mt][0]);
                split_tf32(r1, ah[mt][1], al[mt][1]);
                split_tf32(r2, ah[mt][2], al[mt][2]);
                split_tf32(r3, ah[mt][3], al[mt][3]);
            }
#pragma unroll
            for (int nt = 0; nt < 8; nt++) {
                const int n = ncol + nt * 8 + quad;
                float b0r = Bb[(kk * 8 + tq)     * PADB + n];
                float b1r = Bb[(kk * 8 + tq + 4) * PADB + n];
                uint32_t bh0, bl0, bh1, bl1;
                split_tf32(b0r, bh0, bl0);
                split_tf32(b1r, bh1, bl1);
#pragma unroll
                for (int mt = 0; mt < 2; mt++) {
                    mma_tf32(c[mt][nt], ah[mt], bh0, bh1);
                    mma_tf32(c[mt][nt], ah[mt], bl0, bl1);
                    mma_tf32(c[mt][nt], al[mt], bh0, bh1);
                }
            }
        }
        __syncthreads();
    }

#pragma unroll
    for (int nt = 0; nt < 8; nt++) {
        const int nc = n0 + ncol + nt * 8 + 2 * tq;
        const float bia0 = __ldg(&bias[nc]);
        const float bia1 = __ldg(&bias[nc + 1]);
#pragma unroll
        for (int mt = 0; mt < 2; mt++) {
            const int row0 = m0 + mrow + mt * 16 + quad;
            float2 v01, v23;
            v01.x = fmaxf(c[mt][nt][0] + bia0, 0.f);
            v01.y = fmaxf(c[mt][nt][1] + bia1, 0.f);
            v23.x = fmaxf(c[mt][nt][2] + bia0, 0.f);
            v23.y = fmaxf(c[mt][nt][3] + bia1, 0.f);
            *(float2*)&g_h[(size_t)row0 * N1 + nc]       = v01;
            *(float2*)&g_h[(size_t)(row0 + 8) * N1 + nc] = v23;
        }
    }
}

// ---------------- kernel 2: head GEMM + sigmoid + box decode ----------------
__global__ __launch_bounds__(256, 4)
void head_kernel(const float* __restrict__ ancs,
                 const float* __restrict__ wc, const float* __restrict__ bc,
                 const float* __restrict__ wr, const float* __restrict__ br,
                 float* __restrict__ out) {
    __shared__ float Hs[32][64];
    __shared__ float Ws[32][48];
    __shared__ float Os[64][48];
    const int tid = threadIdx.x;
    const int tx = tid & 15;
    const int ty = tid >> 4;
    const int gr0 = blockIdx.x * 64;

    if (blockIdx.x == 0 && tid == 0) {
        g_prefix = 0ull;
        g_krem = PRE_NMS;
        g_count = 0;
        g_bar_count = 0u;
        g_epoch = 0u;
    }

    float acc[4][3];
#pragma unroll
    for (int i = 0; i < 4; i++)
#pragma unroll
        for (int j = 0; j < 3; j++) acc[i][j] = 0.f;

    for (int k0 = 0; k0 < N1; k0 += 32) {
#pragma unroll
        for (int v = 0; v < 2; v++) {
            int lin = tid * 8 + v * 4;
            int r = lin >> 5;
            int c = lin & 31;
            float4 h4 = *(const float4*)&g_h[(size_t)(gr0 + r) * N1 + k0 + c];
            Hs[c + 0][r] = h4.x; Hs[c + 1][r] = h4.y;
            Hs[c + 2][r] = h4.z; Hs[c + 3][r] = h4.w;
        }
        for (int idx = tid; idx < 32 * 48; idx += 256) {
            int r = idx / 48, o = idx % 48;
            float v = 0.f;
            if (o < 9)       v = wc[(size_t)(k0 + r) * 9 + o];
            else if (o < 45) v = wr[(size_t)(k0 + r) * 36 + (o - 9)];
            Ws[r][o] = v;
        }
        __syncthreads();
#pragma unroll
        for (int k = 0; k < 32; k++) {
            float a0 = Hs[k][ty * 4 + 0], a1 = Hs[k][ty * 4 + 1];
            float a2 = Hs[k][ty * 4 + 2], a3 = Hs[k][ty * 4 + 3];
            float b0 = Ws[k][tx * 3 + 0], b1 = Ws[k][tx * 3 + 1], b2 = Ws[k][tx * 3 + 2];
            acc[0][0] += a0 * b0; acc[0][1] += a0 * b1; acc[0][2] += a0 * b2;
            acc[1][0] += a1 * b0; acc[1][1] += a1 * b1; acc[1][2] += a1 * b2;
            acc[2][0] += a2 * b0; acc[2][1] += a2 * b1; acc[2][2] += a2 * b2;
            acc[3][0] += a3 * b0; acc[3][1] += a3 * b1; acc[3][2] += a3 * b2;
        }
        __syncthreads();
    }
#pragma unroll
    for (int i = 0; i < 4; i++)
#pragma unroll
        for (int j = 0; j < 3; j++) {
            int o = tx * 3 + j;
            float bia = (o < 9) ? bc[o] : ((o < 45) ? br[o - 9] : 0.f);
            Os[ty * 4 + i][o] = acc[i][j] + bia;
        }
    __syncthreads();
    for (int idx = tid; idx < 64 * 45; idx += 256) {
        int r = idx / 45, o = idx % 45;
        float v = Os[r][o];
        int grow = gr0 + r;
        if (o < 9) out[(size_t)grow * 9 + o] = 1.f / (1.f + expf(-v));
        else       out[REG_OFF + (size_t)grow * 36 + (o - 9)] = v;
    }
    for (int t = tid; t < 64 * 9; t += 256) {
        int r = t / 9, a = t % 9;
        int gi = (gr0 + r) * 9 + a;
        float logit = Os[r][a];
        float score = 1.f / (1.f + expf(-logit));
        float tx_ = Os[r][9 + a * 4 + 0];
        float ty_ = Os[r][9 + a * 4 + 1];
        float tw_ = Os[r][9 + a * 4 + 2];
        float th_ = Os[r][9 + a * 4 + 3];
        float acx = ancs[(size_t)gi * 4 + 0];
        float acy = ancs[(size_t)gi * 4 + 1];
        float aw  = ancs[(size_t)gi * 4 + 2];
        float ah  = ancs[(size_t)gi * 4 + 3];
        float cx = acx + tx_ * aw;
        float cy = acy + ty_ * ah;
        float ww = aw * expf(tw_);
        float hh = ah * expf(th_);
        float x1 = fminf(fmaxf(cx - ww * 0.5f, 0.f), 1.f);
        float y1 = fminf(fmaxf(cy - hh * 0.5f, 0.f), 1.f);
        float x2 = fminf(fmaxf(cx + ww * 0.5f, 0.f), 1.f);
        float y2 = fminf(fmaxf(cy + hh * 0.5f, 0.f), 1.f);
        g_boxes[(size_t)gi * 4 + 0] = x1;
        g_boxes[(size_t)gi * 4 + 1] = y1;
        g_boxes[(size_t)gi * 4 + 2] = x2;
        g_boxes[(size_t)gi * 4 + 3] = y2;
        unsigned sb = __float_as_uint(score);
        g_keys[gi] = ((unsigned long long)sb << 32) | (unsigned long long)(~(unsigned)gi);
    }
}

// ===== selection: exact 64-bit radix select + compact, ONE kernel =====
__global__ __launch_bounds__(256)
void select_all() {
    __shared__ unsigned int sh[256];
    __shared__ unsigned long long s_pref;
    __shared__ int s_last;
    const int tid = threadIdx.x;
    const int gs = gridDim.x * blockDim.x;
    const int gi = blockIdx.x * blockDim.x + tid;
    unsigned myep = 0;

    for (int p = 7; p >= 0; p--) {
        const int shift = p * 8;
        if (tid == 0)
            s_pref = (p == 7) ? 0ull : atomicAdd(&g_prefix, 0ull);
        sh[tid] = 0u;
        __syncthreads();
        const unsigned long long pref = s_pref;
        const unsigned long long mask = (p == 7) ? 0ull : (~0ull << (shift + 8));

        for (int i = gi; i < NBOX; i += gs) {
            unsigned long long k = g_keys[i];
            if (((k ^ pref) & mask) == 0ull)
                atomicAdd(&sh[(unsigned)(k >> shift) & 255u], 1u);
        }
        __syncthreads();
        if (sh[tid]) atomicAdd(&g_hist[tid], sh[tid]);
        __threadfence();
        myep++;

        if (tid == 0)
            s_last = (atomicAdd(&g_bar_count, 1u) == (unsigned)(gridDim.x - 1)) ? 1 : 0;
        __syncthreads();

        if (s_last) {
            sh[tid] = atomicAdd(&g_hist[tid], 0u);
            __syncthreads();
            if (tid == 0) {
                int k = atomicAdd(&g_krem, 0);
                int b = 255;
                for (; b >= 0; --b) {
                    int c = (int)sh[b];
                    if (c >= k) break;
                    k -= c;
                }
                if (b < 0) b = 0;
                atomicOr(&g_prefix, ((unsigned long long)(unsigned)b) << shift);
                atomicExch(&g_krem, k);
            }
            atomicExch(&g_hist[tid], 0u);
            __threadfence();
            __syncthreads();
            if (tid == 0) {
                atomicExch(&g_bar_count, 0u);
                __threadfence();
                atomicAdd(&g_epoch, 1u);
            }
        }
        if (tid == 0) {
            while (ld_cg_u32(&g_epoch) < myep) __nanosleep(64);
        }
        __syncthreads();
    }

    if (tid == 0) s_pref = atomicAdd(&g_prefix, 0ull);
    __syncthreads();
    const unsigned long long thr = s_pref;
    for (int i = gi; i < NBOX; i += gs) {
        unsigned long long k = g_keys[i];
        if (k >= thr) {
            int pos = atomicAdd(&g_count, 1);
            if (pos < PRE_NMS) g_ckeys[pos] = k;
        }
    }
}

// ===== NMS stage 1: parallel rank (keys distinct) + scatter boxes =====
#define RANK_ROWS 32
__global__ __launch_bounds__(256, 1)
void rank_kernel() {
    extern __shared__ unsigned long long skey[];   // 6000 * 8 = 48000 B
    __shared__ int scnt[RANK_ROWS];
    const int tid = threadIdx.x;
    const int nvalid = min(g_count, PRE_NMS);

    for (int i = tid; i < PRE_NMS; i += 256)
        skey[i] = (i < nvalid) ? g_ckeys[i] : 0ull;
    if (tid < RANK_ROWS) scnt[tid] = 0;
    __syncthreads();

    const int i0 = blockIdx.x * RANK_ROWS;
    const int e = tid >> 3;          // 0..31
    const int q = tid & 7;
    const int i = i0 + e;
    if (i < nvalid) {
        const unsigned long long ki = skey[i];
        const int j0 = q * (PRE_NMS / 8);
        const int j1 = (q == 7) ? PRE_NMS : j0 + (PRE_NMS / 8);
        int cnt = 0;
        for (int j = j0; j < j1; j++)
            cnt += (skey[j] > ki) ? 1 : 0;
        atomicAdd(&scnt[e], cnt);
    }
    __syncthreads();
    if (tid < RANK_ROWS) {
        const int ii = i0 + tid;
        if (ii < nvalid) {
            const int r = scnt[tid];
            const unsigned gidx = ~(unsigned)skey[ii];
            float4 b = *(const float4*)&g_boxes[(size_t)gidx * 4];
            *(float4*)&g_sboxes[(size_t)r * 4] = b;
        }
    }
}

// ===== NMS stage 2: pairwise IoU bitmask, warp-ballot (conflict-free) =====
// One warp computes one 32-bit mask word: lane jj tests box jbase+jj (consecutive
// SMEM addresses -> no bank conflicts; bi is a broadcast), ballot -> word.
// Upper triangle only (w >= i/32): when a winner is selected it's the minimum
// alive index, so stale bits for j < winner OR into already-removed bits.
#define MASK_ROWS 32
__global__ __launch_bounds__(256, 1)
void mask_kernel() {
    extern __shared__ float4 sbox[];   // 6000 * 16 = 96000 B
    const int tid = threadIdx.x;
    const int lane = tid & 31;
    const int wrp = tid >> 5;          // 0..7
    for (int i = tid; i < PRE_NMS; i += 256)
        sbox[i] = *(const float4*)&g_sboxes[(size_t)i * 4];
    __syncthreads();

    const int i0 = blockIdx.x * MASK_ROWS;
    for (int p = wrp; p < MASK_ROWS * NWORDS; p += 8) {
        const int li = p / NWORDS;
        const int w = p % NWORDS;
        const int i = i0 + li;
        if (i >= PRE_NMS) break;
        if (w < (i >> 5)) continue;            // strict lower-triangle words: never read
        const int j = w * 32 + lane;
        bool sup = false;
        if (j < PRE_NMS) {
            const float4 bi = sbox[i];         // broadcast
            const float4 bj = sbox[j];         // consecutive -> conflict-free
            const float ai = (bi.z - bi.x) * (bi.w - bi.y);
            const float aj = (bj.z - bj.x) * (bj.w - bj.y);
            float iw = fminf(bi.z, bj.z) - fmaxf(bi.x, bj.x);
            float ih = fminf(bi.w, bj.w) - fmaxf(bi.y, bj.y);
            iw = fmaxf(iw, 0.f);
            ih = fmaxf(ih, 0.f);
            const float inter = iw * ih;
            const float uni = ai + aj - inter;
            const float pthr = IOU_THR * uni;
            if (inter > pthr * 1.0001f)      sup = true;
            else if (inter < pthr * 0.9999f) sup = false;
            else {
                const float iou = (uni > 0.f) ? inter / uni : 0.f;
                sup = (iou > IOU_THR);
            }
        }
        const unsigned m = __ballot_sync(0xffffffffu, sup);
        if (lane == 0) g_mask[(size_t)i * NWORDS + w] = m;
    }
}

// ===== NMS stage 3: greedy scan, single warp, bitmap in registers =====
#define SCAN_WPL 6   /* words per lane: 6*32 = 192 >= NWORDS */
__global__ __launch_bounds__(32, 1)
void scan_kernel(float* __restrict__ out) {
    const int lane = threadIdx.x;
    const int nvalid = min(g_count, PRE_NMS);

    unsigned rem[SCAN_WPL];
#pragma unroll
    for (int t = 0; t < SCAN_WPL; t++) {
        const int w = lane + 32 * t;
        unsigned v = 0xFFFFFFFFu;
        if (w < NWORDS) {
            v = 0u;
            const int base = w * 32;
            if (base + 32 > nvalid) {
                for (int b = 0; b < 32; b++)
                    if (base + b >= nvalid) v |= (1u << b);
            }
        }
        rem[t] = v;
    }

    int it = 0;
    for (; it < POST_NMS; it++) {
        int cand = 0x7FFFFFFF;
#pragma unroll
        for (int t = 0; t < SCAN_WPL; t++) {
            const unsigned u = ~rem[t];
            if (u != 0u && cand == 0x7FFFFFFF)
                cand = (lane + 32 * t) * 32 + (__ffs(u) - 1);
        }
#pragma unroll
        for (int off = 16; off > 0; off >>= 1) {
            const int o = __shfl_xor_sync(0xffffffffu, cand, off);
            cand = min(cand, o);
        }
        const int win = cand;
        if (win == 0x7FFFFFFF) break;

        if (lane < 4)
            out[PROP_OFF + it * 4 + lane] = g_sboxes[(size_t)win * 4 + lane];

        const unsigned* row = g_mask + (size_t)win * NWORDS;
#pragma unroll
        for (int t = 0; t < SCAN_WPL; t++) {
            const int w = lane + 32 * t;
            if (w < NWORDS && w >= (win >> 5)) {       // lower-tri words are stale: skip
                unsigned m = row[w];
                if (w == (win >> 5)) {
                    m |= (1u << (win & 31));           // explicit winner clear
                    m &= ~(((1u << (win & 31)) - 1u)); // drop stale sub-winner bits
                }
                rem[t] |= m;
            }
        }
    }
    for (int idx = it * 4 + lane; idx < POST_NMS * 4; idx += 32)
        out[PROP_OFF + idx] = 0.f;
}

// ---------------- launcher ----------------
extern "C" void kernel_launch(void* const* d_in, const int* in_sizes, int n_in,
                              void* d_out, int out_size) {
    const float* feats   = (const float*)d_in[0];
    const float* ancs    = (const float*)d_in[1];
    const float* w_bneck = (const float*)d_in[3];
    const float* b_bneck = (const float*)d_in[4];
    const float* w_cls   = (const float*)d_in[5];
    const float* b_cls   = (const float*)d_in[6];
    const float* w_reg   = (const float*)d_in[7];
    const float* b_reg   = (const float*)d_in[8];
    float* out = (float*)d_out;

    cudaFuncSetAttribute(gemm_bneck_mma, cudaFuncAttributeMaxDynamicSharedMemorySize, GEMM_SMEM);
    cudaFuncSetAttribute(rank_kernel, cudaFuncAttributeMaxDynamicSharedMemorySize, PRE_NMS * 8);
    cudaFuncSetAttribute(mask_kernel, cudaFuncAttributeMaxDynamicSharedMemorySize, PRE_NMS * 16);

    gemm_bneck_mma<<<dim3(4, 128), 256, GEMM_SMEM>>>(feats, w_bneck, b_bneck);
    head_kernel<<<M_ROWS / 64, 256>>>(ancs, w_cls, b_cls, w_reg, b_reg, out);
    select_all<<<SEL_BLOCKS, 256>>>();
    rank_kernel<<<(PRE_NMS + RANK_ROWS - 1) / RANK_ROWS, 256, PRE_NMS * 8>>>();
    mask_kernel<<<(PRE_NMS + MASK_ROWS - 1) / MASK_ROWS, 256, PRE_NMS * 16>>>();
    scan_kernel<<<1, 32>>>(out);
}